// round 1
// baseline (speedup 1.0000x reference)
#include <cuda_runtime.h>
#include <math.h>

// Problem constants (fixed by the dataset: B=32768, K=8, D=256).
#define K_SLOTS 8
#define D_DIM   256
#define THREADS 256
#define MAX_B   32768

// Deterministic per-batch partial losses (no atomics).
__device__ float g_partial[MAX_B];

// ---------------------------------------------------------------------------
// Kernel 1: one CTA per batch element.
//   warp k owns slot-row k of both tensors.
//   ds row k  -> registers (coalesced: lane + 32*i)
//   ss tile   -> shared (every warp needs all 8 ss rows)
//   Gram[k][j] + norms via one butterfly reduction of 10 values.
// ---------------------------------------------------------------------------
__global__ __launch_bounds__(THREADS, 8)
void slot_loss_kernel(const float* __restrict__ ds_g,
                      const float* __restrict__ ss_g,
                      const void*  __restrict__ temp_ptr,
                      float*       __restrict__ partial)
{
    __shared__ float s_ss[K_SLOTS * D_DIM];   // 8 KB
    __shared__ float s_inv[2 * K_SLOTS];
    __shared__ float s_loss[K_SLOTS];

    const int b    = blockIdx.x;
    const int t    = threadIdx.x;
    const int warp = t >> 5;
    const int lane = t & 31;

    const size_t base = (size_t)b * (K_SLOTS * D_DIM);

    // --- temperature: robust f32/f64 scalar read --------------------------
    float invT;
    {
        float f = *(const float*)temp_ptr;
        if (isfinite(f) && f > 1e-8f && f < 1e8f) {
            invT = 1.0f / f;
        } else {
            invT = (float)(1.0 / *(const double*)temp_ptr);
        }
    }

    // --- stage ss tile into shared (float4, coalesced) --------------------
    {
        const float4* src = (const float4*)(ss_g + base);
        float4*       dst = (float4*)s_ss;
        // K*D/4 = 512 float4s, 256 threads -> 2 each
        dst[t]           = src[t];
        dst[t + THREADS] = src[t + THREADS];
    }

    // --- ds row `warp` straight into registers ----------------------------
    float af[8];
    {
        const float* arow = ds_g + base + warp * D_DIM;
#pragma unroll
        for (int i = 0; i < 8; ++i) af[i] = arow[lane + 32 * i];
    }

    __syncthreads();

    // --- partial norms (ds row warp, ss row warp) and Gram row ------------
    float na = 0.f, nb = 0.f;
    {
        const float* brow = s_ss + warp * D_DIM;
#pragma unroll
        for (int i = 0; i < 8; ++i) {
            na = fmaf(af[i], af[i], na);
            float c = brow[lane + 32 * i];
            nb = fmaf(c, c, nb);
        }
    }

    float g[K_SLOTS];
#pragma unroll
    for (int j = 0; j < K_SLOTS; ++j) {
        const float* brow = s_ss + j * D_DIM;
        float acc = 0.f;
#pragma unroll
        for (int i = 0; i < 8; ++i)
            acc = fmaf(af[i], brow[lane + 32 * i], acc);
        g[j] = acc;
    }

    // --- butterfly reduce 10 values across the warp -----------------------
#pragma unroll
    for (int off = 16; off > 0; off >>= 1) {
#pragma unroll
        for (int j = 0; j < K_SLOTS; ++j)
            g[j] += __shfl_xor_sync(0xffffffffu, g[j], off);
        na += __shfl_xor_sync(0xffffffffu, na, off);
        nb += __shfl_xor_sync(0xffffffffu, nb, off);
    }

    if (lane == 0) {
        s_inv[warp]           = 1.0f / fmaxf(sqrtf(na), 1e-12f);  // ds inv-norm
        s_inv[K_SLOTS + warp] = 1.0f / fmaxf(sqrtf(nb), 1e-12f);  // ss inv-norm
    }
    __syncthreads();

    // --- per-row CE: lse - diag -------------------------------------------
    if (lane == 0) {
        const float inva = s_inv[warp];
        float l[K_SLOTS];
        float m = -INFINITY;
#pragma unroll
        for (int j = 0; j < K_SLOTS; ++j) {
            l[j] = g[j] * inva * s_inv[K_SLOTS + j] * invT;
            m = fmaxf(m, l[j]);
        }
        float sum = 0.f;
#pragma unroll
        for (int j = 0; j < K_SLOTS; ++j)
            sum += expf(l[j] - m);
        s_loss[warp] = m + logf(sum) - l[warp];
    }
    __syncthreads();

    if (t == 0) {
        float s = 0.f;
#pragma unroll
        for (int k = 0; k < K_SLOTS; ++k) s += s_loss[k];
        partial[b] = s;
    }
}

// ---------------------------------------------------------------------------
// Kernel 2: deterministic reduction of B partials -> scalar mean / (B*K).
// ---------------------------------------------------------------------------
__global__ __launch_bounds__(THREADS)
void reduce_kernel(const float* __restrict__ partial, float* __restrict__ out,
                   int n, float scale)
{
    __shared__ float sm[THREADS];
    const int t = threadIdx.x;
    float s = 0.f;
    for (int i = t; i < n; i += THREADS) s += partial[i];
    sm[t] = s;
    __syncthreads();
#pragma unroll
    for (int off = THREADS / 2; off > 0; off >>= 1) {
        if (t < off) sm[t] += sm[t + off];
        __syncthreads();
    }
    if (t == 0) out[0] = sm[0] * scale;
}

// ---------------------------------------------------------------------------
extern "C" void kernel_launch(void* const* d_in, const int* in_sizes, int n_in,
                              void* d_out, int out_size)
{
    const float* ds = (const float*)d_in[0];
    const float* ss = (const float*)d_in[1];
    // d_in[2] = labels (unused by the reference math)
    const void* temp_ptr = (n_in > 3) ? d_in[3] : nullptr;

    const int B = in_sizes[0] / (K_SLOTS * D_DIM);

    float* partial;
    cudaGetSymbolAddress((void**)&partial, g_partial);

    slot_loss_kernel<<<B, THREADS>>>(ds, ss, temp_ptr, partial);

    const float scale = 1.0f / ((float)B * (float)K_SLOTS);
    reduce_kernel<<<1, THREADS>>>(partial, (float*)d_out, B, scale);
}

// round 2
// speedup vs baseline: 1.1597x; 1.1597x over previous
#include <cuda_runtime.h>
#include <math.h>

// Problem constants (dataset: B=32768, K=8, D=256, fp32).
#define K_SLOTS   8
#define D_DIM     256
#define THREADS   256
#define NBATCH    2          // batch elements per CTA
#define MAX_PART  32768

// Deterministic per-CTA partial losses (no atomics).
__device__ float g_partial[MAX_PART];

__device__ __forceinline__ float dot8(const float4 a0, const float4 a1,
                                      const float4 b0, const float4 b1) {
    float s;
    s = a0.x * b0.x;
    s = fmaf(a0.y, b0.y, s);
    s = fmaf(a0.z, b0.z, s);
    s = fmaf(a0.w, b0.w, s);
    s = fmaf(a1.x, b1.x, s);
    s = fmaf(a1.y, b1.y, s);
    s = fmaf(a1.z, b1.z, s);
    s = fmaf(a1.w, b1.w, s);
    return s;
}

// ---------------------------------------------------------------------------
// One CTA = 2 batch elements. 4 warps per batch; each warp owns 2 Gram rows.
//   ds rows   -> registers (float4, coalesced)
//   ss tile   -> shared once per batch (float4, coalesced, conflict-free)
//   Gram rows + 2 ds-norms + 2 ss-norms reduced in ONE 20-value butterfly.
// ---------------------------------------------------------------------------
__global__ __launch_bounds__(THREADS, 3)
void slot_loss_kernel(const float* __restrict__ ds_g,
                      const float* __restrict__ ss_g,
                      const void*  __restrict__ temp_ptr,
                      float*       __restrict__ partial,
                      int B)
{
    __shared__ float s_ss[NBATCH * K_SLOTS * D_DIM];   // 16 KB
    __shared__ float s_invb[NBATCH][K_SLOTS];
    __shared__ float s_ce[8];

    const int t    = threadIdx.x;
    const int warp = t >> 5;
    const int lane = t & 31;
    const int wb   = warp >> 2;          // local batch 0/1
    const int h    = warp & 3;           // quarter -> rows 2h, 2h+1
    const int b    = blockIdx.x * NBATCH + wb;
    const bool active = (b < B);

    // --- temperature: robust f32/f64 scalar read ---------------------------
    float invT;
    {
        float f = *(const float*)temp_ptr;
        invT = (isfinite(f) && f > 1e-8f && f < 1e8f)
                 ? (1.0f / f)
                 : (float)(1.0 / *(const double*)temp_ptr);
    }

    // --- ds rows 2h, 2h+1 into registers (independent loads, early) --------
    float4 af[2][2];
    if (active) {
        const size_t dbase = (size_t)b * (K_SLOTS * D_DIM);
#pragma unroll
        for (int r = 0; r < 2; ++r) {
            const float4* arow = (const float4*)(ds_g + dbase + (2 * h + r) * D_DIM);
            af[r][0] = arow[lane];
            af[r][1] = arow[lane + 32];
        }
    } else {
#pragma unroll
        for (int r = 0; r < 2; ++r)
            af[r][0] = af[r][1] = make_float4(0.f, 0.f, 0.f, 0.f);
    }

    // --- cooperative ss stage: 2 contiguous batches, float4 ----------------
    {
        const size_t base0 = (size_t)blockIdx.x * NBATCH * (K_SLOTS * D_DIM);
        const float4* src = (const float4*)(ss_g + base0);
        float4* dst = (float4*)s_ss;
        const int nb_here = min(NBATCH, B - blockIdx.x * NBATCH);
        const int total4  = nb_here * (K_SLOTS * D_DIM / 4);
#pragma unroll
        for (int i = 0; i < NBATCH * K_SLOTS * D_DIM / 4 / THREADS; ++i) {
            int idx = t + i * THREADS;
            if (idx < total4) dst[idx] = src[idx];
        }
    }
    __syncthreads();

    // --- Gram rows + norms --------------------------------------------------
    float na[2], nb[2], acc[2][K_SLOTS];
#pragma unroll
    for (int r = 0; r < 2; ++r)
        na[r] = dot8(af[r][0], af[r][1], af[r][0], af[r][1]);
    nb[0] = nb[1] = 0.f;

    const float4* srow = (const float4*)(s_ss + wb * (K_SLOTS * D_DIM));
#pragma unroll
    for (int j = 0; j < K_SLOTS; ++j) {
        const float4 s0 = srow[j * 64 + lane];
        const float4 s1 = srow[j * 64 + lane + 32];
#pragma unroll
        for (int r = 0; r < 2; ++r)
            acc[r][j] = dot8(af[r][0], af[r][1], s0, s1);
        if (j == 2 * h)     nb[0] = dot8(s0, s1, s0, s1);
        if (j == 2 * h + 1) nb[1] = dot8(s0, s1, s0, s1);
    }

    // --- one butterfly over 20 values ---------------------------------------
#pragma unroll
    for (int off = 16; off > 0; off >>= 1) {
#pragma unroll
        for (int r = 0; r < 2; ++r) {
#pragma unroll
            for (int j = 0; j < K_SLOTS; ++j)
                acc[r][j] += __shfl_xor_sync(0xffffffffu, acc[r][j], off);
            na[r] += __shfl_xor_sync(0xffffffffu, na[r], off);
            nb[r] += __shfl_xor_sync(0xffffffffu, nb[r], off);
        }
    }

    // --- publish ss inverse norms -------------------------------------------
    if (lane == 0) {
#pragma unroll
        for (int r = 0; r < 2; ++r)
            s_invb[wb][2 * h + r] = 1.0f / fmaxf(sqrtf(nb[r]), 1e-12f);
    }
    __syncthreads();

    // --- per-warp CE (2 rows), serial on lane 0 ------------------------------
    if (lane == 0) {
        float ce = 0.f;
        if (active) {
#pragma unroll
            for (int r = 0; r < 2; ++r) {
                const float inva = 1.0f / fmaxf(sqrtf(na[r]), 1e-12f);
                float l[K_SLOTS];
                float m = -INFINITY;
#pragma unroll
                for (int j = 0; j < K_SLOTS; ++j) {
                    l[j] = acc[r][j] * inva * s_invb[wb][j] * invT;
                    m = fmaxf(m, l[j]);
                }
                float sum = 0.f;
#pragma unroll
                for (int j = 0; j < K_SLOTS; ++j)
                    sum += expf(l[j] - m);
                ce += m + logf(sum) - l[2 * h + r];
            }
        }
        s_ce[warp] = ce;
    }
    __syncthreads();

    if (t == 0) {
        float s = 0.f;
#pragma unroll
        for (int w = 0; w < 8; ++w) s += s_ce[w];
        partial[blockIdx.x] = s;
    }
}

// ---------------------------------------------------------------------------
// Deterministic single-block reduction of per-CTA partials.
// ---------------------------------------------------------------------------
#define RTHREADS 1024
__global__ __launch_bounds__(RTHREADS)
void reduce_kernel(const float* __restrict__ partial, float* __restrict__ out,
                   int n, float scale)
{
    __shared__ float sm[RTHREADS];
    const int t = threadIdx.x;
    float s = 0.f;
    for (int i = t; i < n; i += RTHREADS) s += partial[i];
    sm[t] = s;
    __syncthreads();
#pragma unroll
    for (int off = RTHREADS / 2; off > 0; off >>= 1) {
        if (t < off) sm[t] += sm[t + off];
        __syncthreads();
    }
    if (t == 0) out[0] = sm[0] * scale;
}

// ---------------------------------------------------------------------------
extern "C" void kernel_launch(void* const* d_in, const int* in_sizes, int n_in,
                              void* d_out, int out_size)
{
    const float* ds = (const float*)d_in[0];
    const float* ss = (const float*)d_in[1];
    // d_in[2] = labels (unused by the reference math)
    const void* temp_ptr = (n_in > 3) ? d_in[3] : nullptr;

    const int B = in_sizes[0] / (K_SLOTS * D_DIM);
    const int grid = (B + NBATCH - 1) / NBATCH;

    float* partial;
    cudaGetSymbolAddress((void**)&partial, g_partial);

    slot_loss_kernel<<<grid, THREADS>>>(ds, ss, temp_ptr, partial, B);

    const float scale = 1.0f / ((float)B * (float)K_SLOTS);
    reduce_kernel<<<1, RTHREADS>>>(partial, (float*)d_out, grid, scale);
}